// round 7
// baseline (speedup 1.0000x reference)
#include <cuda_runtime.h>
#include <cuda_bf16.h>
#include <cuda_fp16.h>
#include <cstdint>
#include <math.h>

#define BATCH 8
#define LSEQ  2048
#define DDIM  512

// ---------------------------------------------------------------------------
// Device-global scratch (module-load allocation; no runtime allocs).
// ---------------------------------------------------------------------------
static __device__ float g_P[(size_t)BATCH * LSEQ * LSEQ];                       // 128 MiB logits
static __device__ __align__(128) int8_t g_q8h[(size_t)BATCH * LSEQ * DDIM];
static __device__ __align__(128) int8_t g_q8l[(size_t)BATCH * LSEQ * DDIM];
static __device__ __align__(128) int8_t g_k8h[(size_t)BATCH * LSEQ * DDIM];
static __device__ __align__(128) int8_t g_k8l[(size_t)BATCH * LSEQ * DDIM];
static __device__ float g_sq[(size_t)BATCH * LSEQ];                             // per-row scales
static __device__ float g_sk[(size_t)BATCH * LSEQ];
static __device__ __align__(128) __half g_vtf[(size_t)BATCH * DDIM * LSEQ];     // v^T fp16 [b][d][j]
static __device__ __align__(128) __half g_af[(size_t)BATCH * LSEQ * LSEQ];      // attn fp16

// ---------------------------------------------------------------------------
// PTX helpers (sm_80+ only; base sm_103 target has no tcgen05)
// ---------------------------------------------------------------------------
__device__ __forceinline__ uint32_t smem_u32(const void* p) {
    uint32_t a;
    asm("{ .reg .u64 t; cvta.to.shared.u64 t, %1; cvt.u32.u64 %0, t; }" : "=r"(a) : "l"(p));
    return a;
}
__device__ __forceinline__ void ldsm4(uint32_t* r, uint32_t addr) {
    asm volatile("ldmatrix.sync.aligned.m8n8.x4.shared.b16 {%0,%1,%2,%3}, [%4];"
                 : "=r"(r[0]), "=r"(r[1]), "=r"(r[2]), "=r"(r[3]) : "r"(addr));
}
#define MMA_F16(d, a, b0, b1)                                                      \
    asm volatile("mma.sync.aligned.m16n8k16.row.col.f32.f16.f16.f32 "              \
                 "{%0,%1,%2,%3},{%4,%5,%6,%7},{%8,%9},{%0,%1,%2,%3};"              \
                 : "+f"((d)[0]), "+f"((d)[1]), "+f"((d)[2]), "+f"((d)[3])          \
                 : "r"((a)[0]), "r"((a)[1]), "r"((a)[2]), "r"((a)[3]),             \
                   "r"(b0), "r"(b1))
#define MMA_S8(d, a, b0, b1)                                                       \
    asm volatile("mma.sync.aligned.m16n8k32.row.col.s32.s8.s8.s32 "                \
                 "{%0,%1,%2,%3},{%4,%5,%6,%7},{%8,%9},{%0,%1,%2,%3};"              \
                 : "+r"((d)[0]), "+r"((d)[1]), "+r"((d)[2]), "+r"((d)[3])          \
                 : "r"((a)[0]), "r"((a)[1]), "r"((a)[2]), "r"((a)[3]),             \
                   "r"(b0), "r"(b1))
#define CP_ASYNC16(dst, src) \
    asm volatile("cp.async.cg.shared.global [%0], [%1], 16;" :: "r"(dst), "l"(src))
#define CP_COMMIT()  asm volatile("cp.async.commit_group;" ::: "memory")
#define CP_WAITN(n)  asm volatile("cp.async.wait_group %0;" :: "n"(n) : "memory")

// Swizzle for 64-byte rows (4 x 16B segs): seg ^= (row>>1)&3
__device__ __forceinline__ uint32_t swz64(int row, int seg) {
    return (uint32_t)(row * 64 + ((seg ^ ((row >> 1) & 3)) << 4));
}
// Swizzle for 128-byte rows (8 x 16B segs): seg ^= row&7
__device__ __forceinline__ uint32_t swz128(int row, int seg) {
    return (uint32_t)(row * 128 + ((seg ^ (row & 7)) << 4));
}

// ---------------------------------------------------------------------------
// Kernel 1a: per-row int8 hi/lo quantization of q = x*qw and k = x*kw.
// One 128-thread block per (b, i) row; n = round(q/s) in [-16256,16256],
// s = rowmax/16256, qh = round(n/128), ql = n - 128*qh.
// ---------------------------------------------------------------------------
__global__ __launch_bounds__(128) void quant_kernel(const float* __restrict__ x,
                                                    const float* __restrict__ qw,
                                                    const float* __restrict__ kw)
{
    const int i = blockIdx.x;
    const int b = blockIdx.y;
    const int t = threadIdx.x;

    const size_t rx = ((size_t)b * LSEQ + i) * DDIM;
    const float4 xv = *(const float4*)(x  + rx + t * 4);
    const float4 q4r = *(const float4*)(qw + (size_t)i * DDIM + t * 4);
    const float4 k4r = *(const float4*)(kw + (size_t)i * DDIM + t * 4);

    float q[4] = { xv.x * q4r.x, xv.y * q4r.y, xv.z * q4r.z, xv.w * q4r.w };
    float k[4] = { xv.x * k4r.x, xv.y * k4r.y, xv.z * k4r.z, xv.w * k4r.w };

    float mq = 0.f, mk = 0.f;
#pragma unroll
    for (int j = 0; j < 4; ++j) {
        mq = fmaxf(mq, fabsf(q[j]));
        mk = fmaxf(mk, fabsf(k[j]));
    }
#pragma unroll
    for (int o = 16; o > 0; o >>= 1) {
        mq = fmaxf(mq, __shfl_xor_sync(0xffffffffu, mq, o));
        mk = fmaxf(mk, __shfl_xor_sync(0xffffffffu, mk, o));
    }
    __shared__ float smq[4], smk[4];
    const int w = t >> 5;
    if ((t & 31) == 0) { smq[w] = mq; smk[w] = mk; }
    __syncthreads();
    mq = fmaxf(fmaxf(smq[0], smq[1]), fmaxf(smq[2], smq[3]));
    mk = fmaxf(fmaxf(smk[0], smk[1]), fmaxf(smk[2], smk[3]));

    const float invq = 16256.0f / fmaxf(mq, 1e-20f);
    const float invk = 16256.0f / fmaxf(mk, 1e-20f);

    uint32_t ph = 0, pl = 0, kh = 0, kl = 0;
#pragma unroll
    for (int j = 0; j < 4; ++j) {
        int nq = lrintf(q[j] * invq);
        int hq = (nq + 64) >> 7;
        int lq = nq - (hq << 7);
        ph |= (uint32_t)(hq & 0xff) << (j * 8);
        pl |= (uint32_t)(lq & 0xff) << (j * 8);
        int nk = lrintf(k[j] * invk);
        int hk = (nk + 64) >> 7;
        int lk = nk - (hk << 7);
        kh |= (uint32_t)(hk & 0xff) << (j * 8);
        kl |= (uint32_t)(lk & 0xff) << (j * 8);
    }
    *(uint32_t*)(g_q8h + rx + t * 4) = ph;
    *(uint32_t*)(g_q8l + rx + t * 4) = pl;
    *(uint32_t*)(g_k8h + rx + t * 4) = kh;
    *(uint32_t*)(g_k8l + rx + t * 4) = kl;
    if (t == 0) {
        g_sq[(size_t)b * LSEQ + i] = mq * (1.0f / 16256.0f);
        g_sk[(size_t)b * LSEQ + i] = mk * (1.0f / 16256.0f);
    }
}

// ---------------------------------------------------------------------------
// Kernel 1b: v = x*vw -> fp16, transposed [b][d][j]. Block = 64(j) x 64(d).
// ---------------------------------------------------------------------------
__global__ __launch_bounds__(256) void vsplit_kernel(const float* __restrict__ x,
                                                     const float* __restrict__ vw)
{
    __shared__ __half vf_s[64][66];

    const int b  = blockIdx.z;
    const int j0 = blockIdx.x * 64;
    const int d0 = blockIdx.y * 64;
    const int t  = threadIdx.x;

#pragma unroll
    for (int it = 0; it < 4; ++it) {
        const int id = t + it * 256;
        const int r  = id >> 4;
        const int c  = (id & 15) * 4;
        const size_t gx = ((size_t)b * LSEQ + j0 + r) * DDIM + d0 + c;
        const size_t gw = (size_t)(j0 + r) * DDIM + d0 + c;
        const float4 xv = *(const float4*)(x  + gx);
        const float4 v4 = *(const float4*)(vw + gw);
        vf_s[r][c + 0] = __float2half(xv.x * v4.x);
        vf_s[r][c + 1] = __float2half(xv.y * v4.y);
        vf_s[r][c + 2] = __float2half(xv.z * v4.z);
        vf_s[r][c + 3] = __float2half(xv.w * v4.w);
    }
    __syncthreads();

#pragma unroll
    for (int it = 0; it < 16; ++it) {
        const int id = t + it * 256;
        const int dr = id >> 6;
        const int jc = id & 63;
        g_vtf[((size_t)b * DDIM + d0 + dr) * LSEQ + j0 + jc] = vf_s[jc][dr];
    }
}

// ---------------------------------------------------------------------------
// Kernel 2: QK int8 IMMA GEMM, 3 products (hh; cross = h*l + l*h, shared acc).
// Block tile 128(m) x 64(n), K-chunk 64 bytes, 3-stage cp.async, 8 warps in
// 4(m) x 2(n) grid, warp tile 32x32. Writes scaled fp32 logits to g_P.
// ---------------------------------------------------------------------------
__global__ __launch_bounds__(256, 2) void qk_kernel()
{
    extern __shared__ __align__(128) char dsm[];

    constexpr int K       = DDIM;          // 512 bytes per row (int8)
    constexpr int NC      = K / 64;        // 8 chunks
    constexpr int A_B     = 128 * 64;      // 8 KB per A tile
    constexpr int B_B     = 64 * 64;       // 4 KB per B tile
    constexpr int STAGE_B = 2 * A_B + 2 * B_B;   // 24 KB

    const int b  = blockIdx.z;
    const int n0 = blockIdx.x * 64;
    const int m0 = blockIdx.y * 128;
    const int t    = threadIdx.x;
    const int lane = t & 31;
    const int wid  = t >> 5;
    const int wm   = wid & 3;    // 0..3 -> 32-row slab
    const int wn   = wid >> 2;   // 0..1 -> 32-col slab

    const int8_t* pAh = g_q8h + ((size_t)b * LSEQ + m0) * K;
    const int8_t* pAl = g_q8l + ((size_t)b * LSEQ + m0) * K;
    const int8_t* pBh = g_k8h + ((size_t)b * LSEQ + n0) * K;
    const int8_t* pBl = g_k8l + ((size_t)b * LSEQ + n0) * K;
    const float* sq = g_sq + (size_t)b * LSEQ + m0;
    const float* sk = g_sk + (size_t)b * LSEQ + n0;
    float* Cb = g_P + ((size_t)b * LSEQ + m0) * LSEQ + n0;

    const uint32_t sb = smem_u32(dsm);

    // A tiles: 128 rows x 64 B (512 lines); B tiles: 64 x 64 B (256 lines).
    // total per stage = 2*512 + 2*256 = 1536 lines / 256 thr = 6 per thread.
    auto prefetch = [&](int c, int s) {
        const int k0 = c * 64;
        const uint32_t st = sb + s * STAGE_B;
        // A hi/lo: 2 lines per thread each
#pragma unroll
        for (int i = 0; i < 2; ++i) {
            const int li  = t + i * 256;
            const int row = li >> 2;
            const int seg = li & 3;
            const uint32_t o = swz64(row, seg);
            CP_ASYNC16(st + o,           pAh + (size_t)row * K + k0 + seg * 16);
            CP_ASYNC16(st + A_B + o,     pAl + (size_t)row * K + k0 + seg * 16);
        }
        // B hi/lo: 1 line per thread each
        {
            const int row = t >> 2;
            const int seg = t & 3;
            const uint32_t o = swz64(row, seg);
            CP_ASYNC16(st + 2 * A_B + o,       pBh + (size_t)row * K + k0 + seg * 16);
            CP_ASYNC16(st + 2 * A_B + B_B + o, pBl + (size_t)row * K + k0 + seg * 16);
        }
        CP_COMMIT();
    };

    int acc_hh[2][4][4], acc_x[2][4][4];
#pragma unroll
    for (int mf = 0; mf < 2; ++mf)
#pragma unroll
        for (int nf = 0; nf < 4; ++nf)
#pragma unroll
            for (int i = 0; i < 4; ++i) { acc_hh[mf][nf][i] = 0; acc_x[mf][nf][i] = 0; }

    prefetch(0, 0);
    prefetch(1, 1);

    int s = 0;
    for (int c = 0; c < NC; ++c) {
        if (c + 1 < NC) { CP_WAITN(1); } else { CP_WAITN(0); }
        __syncthreads();

        const uint32_t sAh = sb + s * STAGE_B;
        const uint32_t sAl = sAh + A_B;
        const uint32_t sBh = sAh + 2 * A_B;
        const uint32_t sBl = sBh + B_B;

#pragma unroll
        for (int ks = 0; ks < 2; ++ks) {
            // A frags: rows 0-15 at segs (2ks, 2ks+1) via lane mapping
            uint32_t ah[2][4], al[2][4], bh[2][4], bl[2][4];
#pragma unroll
            for (int mf = 0; mf < 2; ++mf) {
                const int row = wm * 32 + mf * 16 + (lane & 15);
                const int seg = 2 * ks + (lane >> 4);
                const uint32_t o = swz64(row, seg);
                ldsm4(ah[mf], sAh + o);
                ldsm4(al[mf], sAl + o);
            }
            // B frags: x4 covers 2 n8 tiles: cols (l>>4)*8 + (l&7), seg 2ks + ((l>>3)&1)
#pragma unroll
            for (int g = 0; g < 2; ++g) {   // g: n8-tile pair (cols 0-15 / 16-31 of warp slab)
                const int col = wn * 32 + g * 16 + ((lane >> 4) << 3) + (lane & 7);
                const int seg = 2 * ks + ((lane >> 3) & 1);
                const uint32_t o = swz64(col, seg);
                ldsm4(bh[g], sBh + o);
                ldsm4(bl[g], sBl + o);
            }
            // bh[g] regs: [tile 2g: b0, b1][tile 2g+1: b0, b1]
#pragma unroll
            for (int mf = 0; mf < 2; ++mf)
#pragma unroll
                for (int nf = 0; nf < 4; ++nf) {
                    const int g = nf >> 1, h = (nf & 1) * 2;
                    MMA_S8(acc_hh[mf][nf], ah[mf], bh[g][h], bh[g][h + 1]);
                }
#pragma unroll
            for (int mf = 0; mf < 2; ++mf)
#pragma unroll
                for (int nf = 0; nf < 4; ++nf) {
                    const int g = nf >> 1, h = (nf & 1) * 2;
                    MMA_S8(acc_x[mf][nf], ah[mf], bl[g][h], bl[g][h + 1]);
                }
#pragma unroll
            for (int mf = 0; mf < 2; ++mf)
#pragma unroll
                for (int nf = 0; nf < 4; ++nf) {
                    const int g = nf >> 1, h = (nf & 1) * 2;
                    MMA_S8(acc_x[mf][nf], al[mf], bh[g][h], bh[g][h + 1]);
                }
        }

        if (c + 2 < NC) {
            int s2 = s + 2; if (s2 >= 3) s2 -= 3;
            prefetch(c + 2, s2);
        }
        if (++s == 3) s = 0;
    }

    // Epilogue: p = 0.35355339 * sq[r] * sk[c] * (16384*hh + 128*x)
    const float smax = 0.3535533905932738f;
#pragma unroll
    for (int mf = 0; mf < 2; ++mf) {
        const int r0 = wm * 32 + mf * 16 + (lane >> 2);
        const float sr0 = smax * sq[r0];
        const float sr8 = smax * sq[r0 + 8];
#pragma unroll
        for (int nf = 0; nf < 4; ++nf) {
            const int cc = wn * 32 + nf * 8 + (lane & 3) * 2;
            const float sc0 = sk[cc], sc1 = sk[cc + 1];
            float2 v0, v1;
            v0.x = sr0 * sc0 * (16384.f * (float)acc_hh[mf][nf][0] + 128.f * (float)acc_x[mf][nf][0]);
            v0.y = sr0 * sc1 * (16384.f * (float)acc_hh[mf][nf][1] + 128.f * (float)acc_x[mf][nf][1]);
            v1.x = sr8 * sc0 * (16384.f * (float)acc_hh[mf][nf][2] + 128.f * (float)acc_x[mf][nf][2]);
            v1.y = sr8 * sc1 * (16384.f * (float)acc_hh[mf][nf][3] + 128.f * (float)acc_x[mf][nf][3]);
            *(float2*)&Cb[(size_t)r0 * LSEQ + cc]       = v0;
            *(float2*)&Cb[(size_t)(r0 + 8) * LSEQ + cc] = v1;
        }
    }
}

// ---------------------------------------------------------------------------
// Kernel 3: row softmax over g_P -> fp16 attention g_af.
// ---------------------------------------------------------------------------
__global__ __launch_bounds__(256) void softmax_kernel()
{
    const size_t row = blockIdx.x;
    const float* p = g_P + row * LSEQ;
    const int t = threadIdx.x;

    __shared__ float red[256];

    float v[8];
    float mx = -1e30f;
#pragma unroll
    for (int i = 0; i < 8; ++i) {
        v[i] = p[t + i * 256];
        mx = fmaxf(mx, v[i]);
    }
    red[t] = mx;
    __syncthreads();
    for (int s = 128; s > 0; s >>= 1) {
        if (t < s) red[t] = fmaxf(red[t], red[t + s]);
        __syncthreads();
    }
    const float m = red[0];
    __syncthreads();

    float sum = 0.0f;
#pragma unroll
    for (int i = 0; i < 8; ++i) {
        v[i] = __expf(v[i] - m);
        sum += v[i];
    }
    red[t] = sum;
    __syncthreads();
    for (int s = 128; s > 0; s >>= 1) {
        if (t < s) red[t] += red[t + s];
        __syncthreads();
    }
    const float inv = 1.0f / red[0];
#pragma unroll
    for (int i = 0; i < 8; ++i)
        g_af[row * LSEQ + t + i * 256] = __float2half(v[i] * inv);
}

// ---------------------------------------------------------------------------
// Kernel 4: AV single-product fp16 HMMA GEMM (unchanged from R6).
// ---------------------------------------------------------------------------
__global__ __launch_bounds__(256, 2) void av_kernel(float* __restrict__ Cout)
{
    extern __shared__ __align__(128) char dsm[];

    constexpr int K       = LSEQ;
    constexpr int NC      = K / 64;        // 32
    constexpr int TILE_B  = 128 * 128;     // 16 KB
    constexpr int STAGE_B = 2 * TILE_B;    // 32 KB

    const int b  = blockIdx.z;
    const int n0 = blockIdx.x * 128;
    const int m0 = blockIdx.y * 128;
    const int t    = threadIdx.x;
    const int lane = t & 31;
    const int wid  = t >> 5;
    const int wm   = wid & 1;
    const int wn   = wid >> 1;

    const __half* pA = g_af  + ((size_t)b * LSEQ + m0) * LSEQ;
    const __half* pB = g_vtf + ((size_t)b * DDIM + n0) * LSEQ;
    float* Cb = Cout + ((size_t)b * LSEQ + m0) * DDIM + n0;

    const uint32_t sb = smem_u32(dsm);

    auto prefetch = [&](int c, int s) {
        const int k0 = c * 64;
        const uint32_t st = sb + s * STAGE_B;
        const __half* gs[2] = { pA + k0, pB + k0 };
#pragma unroll
        for (int tt = 0; tt < 2; ++tt) {
            const uint32_t tb = st + tt * TILE_B;
#pragma unroll
            for (int i = 0; i < 4; ++i) {
                const int li  = t + i * 256;
                const int row = li >> 3;
                const int seg = li & 7;
                CP_ASYNC16(tb + swz128(row, seg), gs[tt] + (size_t)row * LSEQ + seg * 8);
            }
        }
        CP_COMMIT();
    };

    float acc[4][4][4];
#pragma unroll
    for (int mf = 0; mf < 4; ++mf)
#pragma unroll
        for (int nf = 0; nf < 4; ++nf)
#pragma unroll
            for (int i = 0; i < 4; ++i) acc[mf][nf][i] = 0.0f;

    const int lr   = lane & 15;
    const int lseg = lane >> 4;

    prefetch(0, 0);
    prefetch(1, 1);

    int s = 0;
    for (int c = 0; c < NC; ++c) {
        if (c + 1 < NC) { CP_WAITN(1); } else { CP_WAITN(0); }
        __syncthreads();

        const uint32_t sA = sb + s * STAGE_B;
        const uint32_t sB = sA + TILE_B;

#pragma unroll
        for (int ks = 0; ks < 4; ++ks) {
            const int segk = ks * 2 + lseg;
            uint32_t a[4][4], bb[2][4];
#pragma unroll
            for (int mf = 0; mf < 4; ++mf)
                ldsm4(a[mf], sA + swz128(wm * 64 + mf * 16 + lr, segk));
#pragma unroll
            for (int p = 0; p < 2; ++p)
                ldsm4(bb[p], sB + swz128(wn * 32 + p * 16 + lr, segk));
#pragma unroll
            for (int mf = 0; mf < 4; ++mf)
#pragma unroll
                for (int nf = 0; nf < 4; ++nf) {
                    const int p = nf >> 1, s2 = nf & 1;
                    MMA_F16(acc[mf][nf], a[mf], bb[p][s2], bb[p][s2 + 2]);
                }
        }

        if (c + 2 < NC) {
            int s2 = s + 2; if (s2 >= 3) s2 -= 3;
            prefetch(c + 2, s2);
        }
        if (++s == 3) s = 0;
    }

#pragma unroll
    for (int mf = 0; mf < 4; ++mf) {
#pragma unroll
        for (int nf = 0; nf < 4; ++nf) {
            const int r0 = wm * 64 + mf * 16 + (lane >> 2);
            const int cc = wn * 32 + nf * 8 + (lane & 3) * 2;
            float2 v0, v1;
            v0.x = acc[mf][nf][0]; v0.y = acc[mf][nf][1];
            v1.x = acc[mf][nf][2]; v1.y = acc[mf][nf][3];
            *(float2*)&Cb[(size_t)r0 * DDIM + cc]       = v0;
            *(float2*)&Cb[(size_t)(r0 + 8) * DDIM + cc] = v1;
        }
    }
}

// ---------------------------------------------------------------------------
extern "C" void kernel_launch(void* const* d_in, const int* in_sizes, int n_in,
                              void* d_out, int out_size)
{
    const float* x  = (const float*)d_in[0];
    const float* qw = (const float*)d_in[1];
    const float* kw = (const float*)d_in[2];
    const float* vw = (const float*)d_in[3];
    float* out = (float*)d_out;

    constexpr int SMEM_QK = 73728;   // 3 stages x 24 KB
    constexpr int SMEM_AV = 98304;   // 3 stages x 32 KB
    cudaFuncSetAttribute(qk_kernel, cudaFuncAttributeMaxDynamicSharedMemorySize, SMEM_QK);
    cudaFuncSetAttribute(av_kernel, cudaFuncAttributeMaxDynamicSharedMemorySize, SMEM_AV);

    quant_kernel<<<dim3(LSEQ, BATCH), 128>>>(x, qw, kw);
    vsplit_kernel<<<dim3(LSEQ / 64, DDIM / 64, BATCH), 256>>>(x, vw);

    qk_kernel<<<dim3(LSEQ / 64, LSEQ / 128, BATCH), 256, SMEM_QK>>>();

    softmax_kernel<<<BATCH * LSEQ, 256>>>();

    av_kernel<<<dim3(DDIM / 128, LSEQ / 128, BATCH), 256, SMEM_AV>>>(out);
}

// round 8
// speedup vs baseline: 1.9303x; 1.9303x over previous
#include <cuda_runtime.h>
#include <cuda_bf16.h>
#include <cuda_fp16.h>
#include <cstdint>
#include <math.h>

#define BATCH 8
#define LSEQ  2048
#define DDIM  512

// ---------------------------------------------------------------------------
// Device-global scratch (module-load allocation; no runtime allocs).
// ---------------------------------------------------------------------------
static __device__ float g_P[(size_t)BATCH * LSEQ * LSEQ];                           // 128 MiB logits
static __device__ __align__(128) __nv_bfloat16 g_qh[(size_t)BATCH * LSEQ * DDIM];
static __device__ __align__(128) __nv_bfloat16 g_ql[(size_t)BATCH * LSEQ * DDIM];
static __device__ __align__(128) __nv_bfloat16 g_kh[(size_t)BATCH * LSEQ * DDIM];
static __device__ __align__(128) __nv_bfloat16 g_kl[(size_t)BATCH * LSEQ * DDIM];
static __device__ __align__(128) __half g_vtf[(size_t)BATCH * DDIM * LSEQ];         // v^T fp16 [b][d][j]
static __device__ __align__(128) __half g_af[(size_t)BATCH * LSEQ * LSEQ];          // attn fp16

// ---------------------------------------------------------------------------
// PTX helpers (sm_80+ only; base sm_103 target has no tcgen05)
// ---------------------------------------------------------------------------
__device__ __forceinline__ uint32_t smem_u32(const void* p) {
    uint32_t a;
    asm("{ .reg .u64 t; cvta.to.shared.u64 t, %1; cvt.u32.u64 %0, t; }" : "=r"(a) : "l"(p));
    return a;
}
__device__ __forceinline__ void ldsm4(uint32_t* r, uint32_t addr) {
    asm volatile("ldmatrix.sync.aligned.m8n8.x4.shared.b16 {%0,%1,%2,%3}, [%4];"
                 : "=r"(r[0]), "=r"(r[1]), "=r"(r[2]), "=r"(r[3]) : "r"(addr));
}
#define MMA_BF16(d, a, b0, b1)                                                     \
    asm volatile("mma.sync.aligned.m16n8k16.row.col.f32.bf16.bf16.f32 "            \
                 "{%0,%1,%2,%3},{%4,%5,%6,%7},{%8,%9},{%0,%1,%2,%3};"              \
                 : "+f"((d)[0]), "+f"((d)[1]), "+f"((d)[2]), "+f"((d)[3])          \
                 : "r"((a)[0]), "r"((a)[1]), "r"((a)[2]), "r"((a)[3]),             \
                   "r"(b0), "r"(b1))
#define MMA_F16(d, a, b0, b1)                                                      \
    asm volatile("mma.sync.aligned.m16n8k16.row.col.f32.f16.f16.f32 "              \
                 "{%0,%1,%2,%3},{%4,%5,%6,%7},{%8,%9},{%0,%1,%2,%3};"              \
                 : "+f"((d)[0]), "+f"((d)[1]), "+f"((d)[2]), "+f"((d)[3])          \
                 : "r"((a)[0]), "r"((a)[1]), "r"((a)[2]), "r"((a)[3]),             \
                   "r"(b0), "r"(b1))
#define CP_ASYNC16(dst, src) \
    asm volatile("cp.async.cg.shared.global [%0], [%1], 16;" :: "r"(dst), "l"(src))
#define CP_COMMIT()  asm volatile("cp.async.commit_group;" ::: "memory")
#define CP_WAITN(n)  asm volatile("cp.async.wait_group %0;" :: "n"(n) : "memory")

__device__ __forceinline__ void split2(float v, __nv_bfloat16& h, __nv_bfloat16& l) {
    h = __float2bfloat16(v);
    l = __float2bfloat16(v - __bfloat162float(h));
}

// Swizzle for 64-byte rows (4 x 16B segs): seg ^= (row>>1)&3
__device__ __forceinline__ uint32_t swz64(int row, int seg) {
    return (uint32_t)(row * 64 + ((seg ^ ((row >> 1) & 3)) << 4));
}
// Swizzle for 128-byte rows (8 x 16B segs): seg ^= row&7
__device__ __forceinline__ uint32_t swz128(int row, int seg) {
    return (uint32_t)(row * 128 + ((seg ^ (row & 7)) << 4));
}

// ---------------------------------------------------------------------------
// Kernel 1: split projections. q,k -> bf16 hi/lo [b][i][d]; v -> fp16 single,
// transposed [b][d][j] via smem tile transpose. Block = 64(j) x 64(d).
// ---------------------------------------------------------------------------
__global__ __launch_bounds__(256) void split_kernel(const float* __restrict__ x,
                                                    const float* __restrict__ qw,
                                                    const float* __restrict__ kw,
                                                    const float* __restrict__ vw)
{
    __shared__ __half vf_s[64][66];

    const int b  = blockIdx.z;
    const int j0 = blockIdx.x * 64;
    const int d0 = blockIdx.y * 64;
    const int t  = threadIdx.x;

    union U4 { __nv_bfloat16 h[4]; uint2 u; };

#pragma unroll
    for (int it = 0; it < 4; ++it) {
        const int id = t + it * 256;
        const int r  = id >> 4;
        const int c  = (id & 15) * 4;
        const size_t gx = ((size_t)b * LSEQ + j0 + r) * DDIM + d0 + c;
        const size_t gw = (size_t)(j0 + r) * DDIM + d0 + c;
        const float4 xv = *(const float4*)(x  + gx);
        const float4 q4 = *(const float4*)(qw + gw);
        const float4 k4 = *(const float4*)(kw + gw);
        const float4 v4 = *(const float4*)(vw + gw);

        U4 qh, ql, kh, kl;
        split2(xv.x * q4.x, qh.h[0], ql.h[0]); split2(xv.y * q4.y, qh.h[1], ql.h[1]);
        split2(xv.z * q4.z, qh.h[2], ql.h[2]); split2(xv.w * q4.w, qh.h[3], ql.h[3]);
        split2(xv.x * k4.x, kh.h[0], kl.h[0]); split2(xv.y * k4.y, kh.h[1], kl.h[1]);
        split2(xv.z * k4.z, kh.h[2], kl.h[2]); split2(xv.w * k4.w, kh.h[3], kl.h[3]);
        *(uint2*)(g_qh + gx) = qh.u;  *(uint2*)(g_ql + gx) = ql.u;
        *(uint2*)(g_kh + gx) = kh.u;  *(uint2*)(g_kl + gx) = kl.u;

        vf_s[r][c + 0] = __float2half(xv.x * v4.x);
        vf_s[r][c + 1] = __float2half(xv.y * v4.y);
        vf_s[r][c + 2] = __float2half(xv.z * v4.z);
        vf_s[r][c + 3] = __float2half(xv.w * v4.w);
    }
    __syncthreads();

    // Transposed store: 8 halves packed into one 16B store.
#pragma unroll
    for (int it = 0; it < 2; ++it) {
        const int id = t + it * 256;        // 0..511
        const int dr = id >> 3;             // 0..63
        const int jg = (id & 7) * 8;        // 0,8,...,56
        __half tmp[8];
#pragma unroll
        for (int j = 0; j < 8; ++j) tmp[j] = vf_s[jg + j][dr];
        *(uint4*)(g_vtf + ((size_t)b * DDIM + d0 + dr) * LSEQ + j0 + jg) =
            *(const uint4*)tmp;
    }
}

// ---------------------------------------------------------------------------
// Kernel 2: QK 3-product bf16 HMMA GEMM. P = scale * (Qh+Ql)(Kh+Kl)^T (lo*lo
// dropped). Tile 128x128, K-chunk 32, 3-stage cp.async, one barrier per chunk.
// ---------------------------------------------------------------------------
__global__ __launch_bounds__(256, 2) void qk_kernel()
{
    extern __shared__ __align__(128) char dsm[];

    constexpr int K       = DDIM;
    constexpr int NC      = K / 32;        // 16
    constexpr int TILE_B  = 128 * 64;      // 8 KB
    constexpr int STAGE_B = 4 * TILE_B;    // 32 KB
    const float scale = 0.3535533905932738f;

    const int b  = blockIdx.z;
    const int n0 = blockIdx.x * 128;
    const int m0 = blockIdx.y * 128;
    const int t    = threadIdx.x;
    const int lane = t & 31;
    const int wid  = t >> 5;
    const int wm   = wid & 1;
    const int wn   = wid >> 1;

    const __nv_bfloat16* pAh = g_qh + ((size_t)b * LSEQ + m0) * K;
    const __nv_bfloat16* pAl = g_ql + ((size_t)b * LSEQ + m0) * K;
    const __nv_bfloat16* pBh = g_kh + ((size_t)b * LSEQ + n0) * K;
    const __nv_bfloat16* pBl = g_kl + ((size_t)b * LSEQ + n0) * K;
    float* Cb = g_P + ((size_t)b * LSEQ + m0) * LSEQ + n0;

    const uint32_t sb = smem_u32(dsm);

    auto prefetch = [&](int c, int s) {
        const int k0 = c * 32;
        const uint32_t st = sb + s * STAGE_B;
        const __nv_bfloat16* gs[4] = { pAh + k0, pAl + k0, pBh + k0, pBl + k0 };
#pragma unroll
        for (int tt = 0; tt < 4; ++tt) {
            const uint32_t tb = st + tt * TILE_B;
#pragma unroll
            for (int i = 0; i < 2; ++i) {
                const int li  = t + i * 256;
                const int row = li >> 2;
                const int seg = li & 3;
                CP_ASYNC16(tb + swz64(row, seg), gs[tt] + (size_t)row * K + seg * 8);
            }
        }
        CP_COMMIT();
    };

    float acc[4][4][4];
#pragma unroll
    for (int mf = 0; mf < 4; ++mf)
#pragma unroll
        for (int nf = 0; nf < 4; ++nf)
#pragma unroll
            for (int i = 0; i < 4; ++i) acc[mf][nf][i] = 0.0f;

    const int lr   = lane & 15;
    const int lseg = lane >> 4;

    prefetch(0, 0);
    prefetch(1, 1);

    int s = 0;
    for (int c = 0; c < NC; ++c) {
        if (c + 1 < NC) { CP_WAITN(1); } else { CP_WAITN(0); }
        __syncthreads();

        const uint32_t st  = sb + s * STAGE_B;
        const uint32_t sAh = st;
        const uint32_t sAl = st + TILE_B;
        const uint32_t sBh = st + 2 * TILE_B;
        const uint32_t sBl = st + 3 * TILE_B;

#pragma unroll
        for (int ks = 0; ks < 2; ++ks) {
            const int segk = ks * 2 + lseg;
            uint32_t ah[4][4], al[4][4], bh[2][4], bl[2][4];
#pragma unroll
            for (int mf = 0; mf < 4; ++mf) {
                const uint32_t off = swz64(wm * 64 + mf * 16 + lr, segk);
                ldsm4(ah[mf], sAh + off);
                ldsm4(al[mf], sAl + off);
            }
#pragma unroll
            for (int p = 0; p < 2; ++p) {
                const uint32_t off = swz64(wn * 32 + p * 16 + lr, segk);
                ldsm4(bh[p], sBh + off);
                ldsm4(bl[p], sBl + off);
            }
#pragma unroll
            for (int mf = 0; mf < 4; ++mf)
#pragma unroll
                for (int nf = 0; nf < 4; ++nf) {
                    const int p = nf >> 1, s2 = nf & 1;
                    MMA_BF16(acc[mf][nf], ah[mf], bh[p][s2], bh[p][s2 + 2]);
                }
#pragma unroll
            for (int mf = 0; mf < 4; ++mf)
#pragma unroll
                for (int nf = 0; nf < 4; ++nf) {
                    const int p = nf >> 1, s2 = nf & 1;
                    MMA_BF16(acc[mf][nf], al[mf], bh[p][s2], bh[p][s2 + 2]);
                }
#pragma unroll
            for (int mf = 0; mf < 4; ++mf)
#pragma unroll
                for (int nf = 0; nf < 4; ++nf) {
                    const int p = nf >> 1, s2 = nf & 1;
                    MMA_BF16(acc[mf][nf], ah[mf], bl[p][s2], bl[p][s2 + 2]);
                }
        }

        if (c + 2 < NC) {
            int s2 = s + 2; if (s2 >= 3) s2 -= 3;
            prefetch(c + 2, s2);
        }
        if (++s == 3) s = 0;
    }

#pragma unroll
    for (int mf = 0; mf < 4; ++mf) {
#pragma unroll
        for (int nf = 0; nf < 4; ++nf) {
            const int r0 = wm * 64 + mf * 16 + (lane >> 2);
            const int cc = wn * 32 + nf * 8 + (lane & 3) * 2;
            float2 v0, v1;
            v0.x = acc[mf][nf][0] * scale; v0.y = acc[mf][nf][1] * scale;
            v1.x = acc[mf][nf][2] * scale; v1.y = acc[mf][nf][3] * scale;
            *(float2*)&Cb[(size_t)r0 * LSEQ + cc]       = v0;
            *(float2*)&Cb[(size_t)(r0 + 8) * LSEQ + cc] = v1;
        }
    }
}

// ---------------------------------------------------------------------------
// Kernel 3: row softmax over g_P -> fp16 attention g_af.
// 8 consecutive cols per thread: float4 loads, packed uint4 half stores.
// ---------------------------------------------------------------------------
__global__ __launch_bounds__(256) void softmax_kernel()
{
    const size_t row = blockIdx.x;
    const float* p = g_P + row * LSEQ;
    const int t = threadIdx.x;

    __shared__ float red[256];

    float v[8];
    {
        const float4 a = ((const float4*)p)[t * 2];
        const float4 b = ((const float4*)p)[t * 2 + 1];
        v[0] = a.x; v[1] = a.y; v[2] = a.z; v[3] = a.w;
        v[4] = b.x; v[5] = b.y; v[6] = b.z; v[7] = b.w;
    }
    float mx = v[0];
#pragma unroll
    for (int i = 1; i < 8; ++i) mx = fmaxf(mx, v[i]);
    red[t] = mx;
    __syncthreads();
    for (int s = 128; s > 0; s >>= 1) {
        if (t < s) red[t] = fmaxf(red[t], red[t + s]);
        __syncthreads();
    }
    const float m = red[0];
    __syncthreads();

    float sum = 0.0f;
#pragma unroll
    for (int i = 0; i < 8; ++i) {
        v[i] = __expf(v[i] - m);
        sum += v[i];
    }
    red[t] = sum;
    __syncthreads();
    for (int s = 128; s > 0; s >>= 1) {
        if (t < s) red[t] += red[t + s];
        __syncthreads();
    }
    const float inv = 1.0f / red[0];

    __half h[8];
#pragma unroll
    for (int i = 0; i < 8; ++i) h[i] = __float2half(v[i] * inv);
    *(uint4*)(g_af + row * LSEQ + t * 8) = *(const uint4*)h;
}

// ---------------------------------------------------------------------------
// Kernel 4: AV single-product fp16 HMMA GEMM.
// Tile 128x128, K-chunk 64 (128-byte rows, SW128), 3-stage cp.async.
// ---------------------------------------------------------------------------
__global__ __launch_bounds__(256, 2) void av_kernel(float* __restrict__ Cout)
{
    extern __shared__ __align__(128) char dsm[];

    constexpr int K       = LSEQ;
    constexpr int NC      = K / 64;        // 32
    constexpr int TILE_B  = 128 * 128;     // 16 KB
    constexpr int STAGE_B = 2 * TILE_B;    // 32 KB

    const int b  = blockIdx.z;
    const int n0 = blockIdx.x * 128;
    const int m0 = blockIdx.y * 128;
    const int t    = threadIdx.x;
    const int lane = t & 31;
    const int wid  = t >> 5;
    const int wm   = wid & 1;
    const int wn   = wid >> 1;

    const __half* pA = g_af  + ((size_t)b * LSEQ + m0) * LSEQ;
    const __half* pB = g_vtf + ((size_t)b * DDIM + n0) * LSEQ;
    float* Cb = Cout + ((size_t)b * LSEQ + m0) * DDIM + n0;

    const uint32_t sb = smem_u32(dsm);

    auto prefetch = [&](int c, int s) {
        const int k0 = c * 64;
        const uint32_t st = sb + s * STAGE_B;
        const __half* gs[2] = { pA + k0, pB + k0 };
#pragma unroll
        for (int tt = 0; tt < 2; ++tt) {
            const uint32_t tb = st + tt * TILE_B;
#pragma unroll
            for (int i = 0; i < 4; ++i) {
                const int li  = t + i * 256;
                const int row = li >> 3;
                const int seg = li & 7;
                CP_ASYNC16(tb + swz128(row, seg), gs[tt] + (size_t)row * LSEQ + seg * 8);
            }
        }
        CP_COMMIT();
    };

    float acc[4][4][4];
#pragma unroll
    for (int mf = 0; mf < 4; ++mf)
#pragma unroll
        for (int nf = 0; nf < 4; ++nf)
#pragma unroll
            for (int i = 0; i < 4; ++i) acc[mf][nf][i] = 0.0f;

    const int lr   = lane & 15;
    const int lseg = lane >> 4;

    prefetch(0, 0);
    prefetch(1, 1);

    int s = 0;
    for (int c = 0; c < NC; ++c) {
        if (c + 1 < NC) { CP_WAITN(1); } else { CP_WAITN(0); }
        __syncthreads();

        const uint32_t sA = sb + s * STAGE_B;
        const uint32_t sB = sA + TILE_B;

#pragma unroll
        for (int ks = 0; ks < 4; ++ks) {
            const int segk = ks * 2 + lseg;
            uint32_t a[4][4], bb[2][4];
#pragma unroll
            for (int mf = 0; mf < 4; ++mf)
                ldsm4(a[mf], sA + swz128(wm * 64 + mf * 16 + lr, segk));
#pragma unroll
            for (int p = 0; p < 2; ++p)
                ldsm4(bb[p], sB + swz128(wn * 32 + p * 16 + lr, segk));
#pragma unroll
            for (int mf = 0; mf < 4; ++mf)
#pragma unroll
                for (int nf = 0; nf < 4; ++nf) {
                    const int p = nf >> 1, s2 = nf & 1;
                    MMA_F16(acc[mf][nf], a[mf], bb[p][s2], bb[p][s2 + 2]);
                }
        }

        if (c + 2 < NC) {
            int s2 = s + 2; if (s2 >= 3) s2 -= 3;
            prefetch(c + 2, s2);
        }
        if (++s == 3) s = 0;
    }

#pragma unroll
    for (int mf = 0; mf < 4; ++mf) {
#pragma unroll
        for (int nf = 0; nf < 4; ++nf) {
            const int r0 = wm * 64 + mf * 16 + (lane >> 2);
            const int cc = wn * 32 + nf * 8 + (lane & 3) * 2;
            float2 v0, v1;
            v0.x = acc[mf][nf][0]; v0.y = acc[mf][nf][1];
            v1.x = acc[mf][nf][2]; v1.y = acc[mf][nf][3];
            *(float2*)&Cb[(size_t)r0 * DDIM + cc]       = v0;
            *(float2*)&Cb[(size_t)(r0 + 8) * DDIM + cc] = v1;
        }
    }
}

// ---------------------------------------------------------------------------
extern "C" void kernel_launch(void* const* d_in, const int* in_sizes, int n_in,
                              void* d_out, int out_size)
{
    const float* x  = (const float*)d_in[0];
    const float* qw = (const float*)d_in[1];
    const float* kw = (const float*)d_in[2];
    const float* vw = (const float*)d_in[3];
    float* out = (float*)d_out;

    constexpr int SMEM = 98304;   // 3 stages x 32 KB
    cudaFuncSetAttribute(qk_kernel, cudaFuncAttributeMaxDynamicSharedMemorySize, SMEM);
    cudaFuncSetAttribute(av_kernel, cudaFuncAttributeMaxDynamicSharedMemorySize, SMEM);

    split_kernel<<<dim3(LSEQ / 64, DDIM / 64, BATCH), 256>>>(x, qw, kw, vw);

    qk_kernel<<<dim3(LSEQ / 128, LSEQ / 128, BATCH), 256, SMEM>>>();

    softmax_kernel<<<BATCH * LSEQ, 256>>>();

    av_kernel<<<dim3(DDIM / 128, LSEQ / 128, BATCH), 256, SMEM>>>(out);
}